// round 1
// baseline (speedup 1.0000x reference)
#include <cuda_runtime.h>
#include <cuda_bf16.h>

#define NNODES 100000
#define NEDGES 1600000
#define DIM 64
#define HID 128
#define ODIM 64
#define GEPS 1e-7f
#define BN_EPSC 1e-5f
#define NORM_EPSC 1e-12f

// -------- scratch (device globals; no allocation allowed) --------
__device__ float g_num[NNODES * DIM];     // sum(ex*m) per (node, ch)
__device__ float g_den[NNODES * DIM];     // sum(ex)   per (node, ch)
__device__ float g_x[NNODES * DIM];       // post-MessageNorm features
__device__ float g_hidden[NNODES * HID];  // GEMM1 output (pre-BN)
__device__ float g_bnsum[HID];
__device__ float g_bnsq[HID];
__device__ float g_ab[2 * HID];           // per-channel BN affine: a, b

// -------- kernel 0: zero accumulators (must re-zero every launch) --------
__global__ void zero_kernel() {
    int i = blockIdx.x * blockDim.x + threadIdx.x;  // 1.6M threads
    float4 z = make_float4(0.f, 0.f, 0.f, 0.f);
    ((float4*)g_num)[i] = z;
    ((float4*)g_den)[i] = z;
    if (i < HID) { g_bnsum[i] = 0.f; g_bnsq[i] = 0.f; }
}

// -------- kernel 1: single pass over edges --------
// m = relu(feats[src]+e)+eps ; ex = exp(m) (softmax shift dropped: m in (0,~9])
// den[dst] += ex ; num[dst] += ex*m   via float4 vector reductions
__global__ void edge_kernel(const float* __restrict__ feats,
                            const float* __restrict__ eh,
                            const int* __restrict__ src,
                            const int* __restrict__ dst) {
    int t = blockIdx.x * blockDim.x + threadIdx.x;  // E*16 = 25.6M exactly
    int e = t >> 4;
    int c = (t & 15) << 2;
    int s = __ldg(src + e);
    int d = __ldg(dst + e);
    float4 f  = *(const float4*)(feats + (size_t)s * DIM + c);
    float4 ev = *(const float4*)(eh + (size_t)e * DIM + c);
    float m0 = fmaxf(f.x + ev.x, 0.f) + GEPS;
    float m1 = fmaxf(f.y + ev.y, 0.f) + GEPS;
    float m2 = fmaxf(f.z + ev.z, 0.f) + GEPS;
    float m3 = fmaxf(f.w + ev.w, 0.f) + GEPS;
    float e0 = __expf(m0), e1 = __expf(m1), e2 = __expf(m2), e3 = __expf(m3);
    size_t o = (size_t)d * DIM + c;
    atomicAdd((float4*)(g_den + o), make_float4(e0, e1, e2, e3));
    atomicAdd((float4*)(g_num + o), make_float4(e0 * m0, e1 * m1, e2 * m2, e3 * m3));
}

// -------- kernel 2: h = num/den; MessageNorm; x = feats + h_hat*||f||*scale --------
__global__ void msgnorm_kernel(const float* __restrict__ feats,
                               const float* __restrict__ scale) {
    int t = blockIdx.x * blockDim.x + threadIdx.x;  // N*16 = 1.6M exactly
    int n = t >> 4;
    int c = (t & 15) << 2;
    size_t o = (size_t)n * DIM + c;
    float4 nu = *(const float4*)(g_num + o);
    float4 de = *(const float4*)(g_den + o);
    float4 h;
    h.x = de.x > 0.f ? nu.x / de.x : 0.f;
    h.y = de.y > 0.f ? nu.y / de.y : 0.f;
    h.z = de.z > 0.f ? nu.z / de.z : 0.f;
    h.w = de.w > 0.f ? nu.w / de.w : 0.f;
    float4 f = *(const float4*)(feats + o);
    float hs = h.x * h.x + h.y * h.y + h.z * h.z + h.w * h.w;
    float fs = f.x * f.x + f.y * f.y + f.z * f.z + f.w * f.w;
    #pragma unroll
    for (int off = 8; off; off >>= 1) {
        hs += __shfl_xor_sync(0xffffffffu, hs, off);
        fs += __shfl_xor_sync(0xffffffffu, fs, off);
    }
    float k = sqrtf(fs) * __ldg(scale) / fmaxf(sqrtf(hs), NORM_EPSC);
    float4 x = make_float4(f.x + h.x * k, f.y + h.y * k, f.z + h.z * k, f.w + h.w * k);
    *(float4*)(g_x + o) = x;
}

// -------- kernel 3: hidden = x@W1+b1, plus BN stats (sum, sumsq per channel) ----
// tile: 64 nodes x 128 hid, K=64 split in 2 chunks of 32. 256 thr, each 4x8.
__global__ void __launch_bounds__(256) gemm1_kernel(const float* __restrict__ W1,
                                                    const float* __restrict__ b1) {
    __shared__ float sw[32 * HID];     // 16 KB
    __shared__ float sx[64 * 36];      // 9 KB (pad 36)
    __shared__ float red_s[HID];
    __shared__ float red_q[HID];
    int tid = threadIdx.x;
    int ty = tid >> 4, tx = tid & 15;
    int m0 = blockIdx.x * 64;
    float acc[4][8];
    #pragma unroll
    for (int i = 0; i < 4; i++)
        #pragma unroll
        for (int j = 0; j < 8; j++) acc[i][j] = 0.f;

    for (int kc = 0; kc < 2; kc++) {
        int k0 = kc * 32;
        __syncthreads();
        // W1 chunk: rows k0..k0+31, 128 cols => 1024 float4 / 256 thr = 4 each
        #pragma unroll
        for (int p = 0; p < 4; p++)
            ((float4*)sw)[tid + p * 256] =
                ((const float4*)(W1 + (size_t)k0 * HID))[tid + p * 256];
        // x chunk: 64 rows x 32 cols => 512 float4, 2 per thread
        #pragma unroll
        for (int p = 0; p < 2; p++) {
            int r = (tid >> 3) + p * 32;
            int q = tid & 7;
            int n = m0 + r;
            float4 v = make_float4(0.f, 0.f, 0.f, 0.f);
            if (n < NNODES) v = *(const float4*)(g_x + (size_t)n * DIM + k0 + q * 4);
            *(float4*)(sx + r * 36 + q * 4) = v;
        }
        __syncthreads();
        #pragma unroll
        for (int k = 0; k < 32; k++) {
            float a0 = sx[(ty * 4 + 0) * 36 + k];
            float a1 = sx[(ty * 4 + 1) * 36 + k];
            float a2 = sx[(ty * 4 + 2) * 36 + k];
            float a3 = sx[(ty * 4 + 3) * 36 + k];
            float4 w0 = *(float4*)(sw + k * HID + tx * 8);
            float4 w1 = *(float4*)(sw + k * HID + tx * 8 + 4);
            acc[0][0] += a0 * w0.x; acc[0][1] += a0 * w0.y; acc[0][2] += a0 * w0.z; acc[0][3] += a0 * w0.w;
            acc[0][4] += a0 * w1.x; acc[0][5] += a0 * w1.y; acc[0][6] += a0 * w1.z; acc[0][7] += a0 * w1.w;
            acc[1][0] += a1 * w0.x; acc[1][1] += a1 * w0.y; acc[1][2] += a1 * w0.z; acc[1][3] += a1 * w0.w;
            acc[1][4] += a1 * w1.x; acc[1][5] += a1 * w1.y; acc[1][6] += a1 * w1.z; acc[1][7] += a1 * w1.w;
            acc[2][0] += a2 * w0.x; acc[2][1] += a2 * w0.y; acc[2][2] += a2 * w0.z; acc[2][3] += a2 * w0.w;
            acc[2][4] += a2 * w1.x; acc[2][5] += a2 * w1.y; acc[2][6] += a2 * w1.z; acc[2][7] += a2 * w1.w;
            acc[3][0] += a3 * w0.x; acc[3][1] += a3 * w0.y; acc[3][2] += a3 * w0.z; acc[3][3] += a3 * w0.w;
            acc[3][4] += a3 * w1.x; acc[3][5] += a3 * w1.y; acc[3][6] += a3 * w1.z; acc[3][7] += a3 * w1.w;
        }
    }
    __syncthreads();
    if (tid < HID) { red_s[tid] = 0.f; red_q[tid] = 0.f; }
    __syncthreads();

    float bb[8];
    #pragma unroll
    for (int j = 0; j < 8; j++) bb[j] = __ldg(b1 + tx * 8 + j);
    float ps[8], pq[8];
    #pragma unroll
    for (int j = 0; j < 8; j++) { ps[j] = 0.f; pq[j] = 0.f; }
    #pragma unroll
    for (int i = 0; i < 4; i++) {
        int n = m0 + ty * 4 + i;
        if (n < NNODES) {
            float h[8];
            #pragma unroll
            for (int j = 0; j < 8; j++) {
                h[j] = acc[i][j] + bb[j];
                ps[j] += h[j];
                pq[j] += h[j] * h[j];
            }
            float* dstp = g_hidden + (size_t)n * HID + tx * 8;
            *(float4*)(dstp)     = make_float4(h[0], h[1], h[2], h[3]);
            *(float4*)(dstp + 4) = make_float4(h[4], h[5], h[6], h[7]);
        }
    }
    #pragma unroll
    for (int j = 0; j < 8; j++) {
        atomicAdd(&red_s[tx * 8 + j], ps[j]);
        atomicAdd(&red_q[tx * 8 + j], pq[j]);
    }
    __syncthreads();
    if (tid < HID) {
        atomicAdd(&g_bnsum[tid], red_s[tid]);
        atomicAdd(&g_bnsq[tid], red_q[tid]);
    }
}

// -------- kernel 4: finalize BN affine --------
__global__ void bnfin_kernel(const float* __restrict__ gamma,
                             const float* __restrict__ beta) {
    int c = threadIdx.x;
    float mean = g_bnsum[c] * (1.0f / NNODES);
    float var = g_bnsq[c] * (1.0f / NNODES) - mean * mean;
    float inv = rsqrtf(var + BN_EPSC);
    float a = __ldg(gamma + c) * inv;
    g_ab[c] = a;
    g_ab[HID + c] = __ldg(beta + c) - mean * a;
}

// -------- kernel 5: out = relu(bn(hidden)) @ W2 + b2 --------
// tile 64 nodes x 64 out, K=128 split in 4 chunks of 32. 256 thr, each 4x4.
__global__ void __launch_bounds__(256) gemm2_kernel(const float* __restrict__ W2,
                                                    const float* __restrict__ b2,
                                                    float* __restrict__ out) {
    __shared__ float sw[32 * ODIM];    // 8 KB
    __shared__ float sh[64 * 36];      // 9 KB
    __shared__ float sab[2 * HID];
    int tid = threadIdx.x;
    int ty = tid >> 4, tx = tid & 15;
    int m0 = blockIdx.x * 64;
    sab[tid] = g_ab[tid];  // 256 == 2*HID
    float acc[4][4];
    #pragma unroll
    for (int i = 0; i < 4; i++)
        #pragma unroll
        for (int j = 0; j < 4; j++) acc[i][j] = 0.f;

    for (int kc = 0; kc < 4; kc++) {
        int k0 = kc * 32;
        __syncthreads();
        // W2 chunk: 32 rows x 64 cols => 512 float4, 2 per thread
        #pragma unroll
        for (int p = 0; p < 2; p++)
            ((float4*)sw)[tid + p * 256] =
                ((const float4*)(W2 + (size_t)k0 * ODIM))[tid + p * 256];
        // hidden chunk with BN+ReLU applied on load
        #pragma unroll
        for (int p = 0; p < 2; p++) {
            int r = (tid >> 3) + p * 32;
            int q = tid & 7;
            int n = m0 + r;
            int ch = k0 + q * 4;
            float4 v = make_float4(0.f, 0.f, 0.f, 0.f);
            if (n < NNODES) {
                v = *(const float4*)(g_hidden + (size_t)n * HID + ch);
                v.x = fmaxf(v.x * sab[ch + 0] + sab[HID + ch + 0], 0.f);
                v.y = fmaxf(v.y * sab[ch + 1] + sab[HID + ch + 1], 0.f);
                v.z = fmaxf(v.z * sab[ch + 2] + sab[HID + ch + 2], 0.f);
                v.w = fmaxf(v.w * sab[ch + 3] + sab[HID + ch + 3], 0.f);
            }
            *(float4*)(sh + r * 36 + q * 4) = v;
        }
        __syncthreads();
        #pragma unroll
        for (int k = 0; k < 32; k++) {
            float a0 = sh[(ty * 4 + 0) * 36 + k];
            float a1 = sh[(ty * 4 + 1) * 36 + k];
            float a2 = sh[(ty * 4 + 2) * 36 + k];
            float a3 = sh[(ty * 4 + 3) * 36 + k];
            float4 w = *(float4*)(sw + k * ODIM + tx * 4);
            acc[0][0] += a0 * w.x; acc[0][1] += a0 * w.y; acc[0][2] += a0 * w.z; acc[0][3] += a0 * w.w;
            acc[1][0] += a1 * w.x; acc[1][1] += a1 * w.y; acc[1][2] += a1 * w.z; acc[1][3] += a1 * w.w;
            acc[2][0] += a2 * w.x; acc[2][1] += a2 * w.y; acc[2][2] += a2 * w.z; acc[2][3] += a2 * w.w;
            acc[3][0] += a3 * w.x; acc[3][1] += a3 * w.y; acc[3][2] += a3 * w.z; acc[3][3] += a3 * w.w;
        }
    }
    float4 bv = *(const float4*)(b2 + tx * 4);
    #pragma unroll
    for (int i = 0; i < 4; i++) {
        int n = m0 + ty * 4 + i;
        if (n < NNODES) {
            float4 o = make_float4(acc[i][0] + bv.x, acc[i][1] + bv.y,
                                   acc[i][2] + bv.z, acc[i][3] + bv.w);
            *(float4*)(out + (size_t)n * ODIM + tx * 4) = o;
        }
    }
}

// -------- host launcher --------
extern "C" void kernel_launch(void* const* d_in, const int* in_sizes, int n_in,
                              void* d_out, int out_size) {
    const float *feats = nullptr, *edge_h = nullptr, *W1 = nullptr, *b1 = nullptr;
    const float *gamma = nullptr, *bnb = nullptr, *W2 = nullptr, *b2 = nullptr, *scale = nullptr;
    const int *src = nullptr, *dst = nullptr;
    int nE = 0, nW = 0, nH = 0;
    for (int i = 0; i < n_in; i++) {
        int s = in_sizes[i];
        const void* p = d_in[i];
        if (s == NNODES * DIM) feats = (const float*)p;
        else if (s == NEDGES * DIM) edge_h = (const float*)p;
        else if (s == NEDGES) { if (nE++ == 0) src = (const int*)p; else dst = (const int*)p; }
        else if (s == DIM * HID) { if (nW++ == 0) W1 = (const float*)p; else W2 = (const float*)p; }
        else if (s == HID) {
            if (nH == 0) b1 = (const float*)p;
            else if (nH == 1) gamma = (const float*)p;
            else bnb = (const float*)p;
            nH++;
        }
        else if (s == ODIM) b2 = (const float*)p;
        else if (s == 1) scale = (const float*)p;
    }

    zero_kernel<<<(NNODES * DIM / 4 + 255) / 256, 256>>>();
    edge_kernel<<<(NEDGES * 16) / 256, 256>>>(feats, edge_h, src, dst);
    msgnorm_kernel<<<(NNODES * 16) / 256, 256>>>(feats, scale);
    gemm1_kernel<<<(NNODES + 63) / 64, 256>>>(W1, b1);
    bnfin_kernel<<<1, HID>>>(gamma, bnb);
    gemm2_kernel<<<(NNODES + 63) / 64, 256>>>(W2, b2, (float*)d_out);
}

// round 4
// speedup vs baseline: 1.0717x; 1.0717x over previous
#include <cuda_runtime.h>
#include <cuda_bf16.h>

#define NNODES 100000
#define NEDGES 1600000
#define DIM 64
#define HID 128
#define ODIM 64
#define GEPS 1e-7f
#define BN_EPSC 1e-5f
#define NORM_EPSC 1e-12f

// -------- scratch (device globals; no allocation allowed) --------
__device__ float g_num[NNODES * DIM];     // sum(ex*m) per (node, ch)
__device__ float g_den[NNODES * DIM];     // sum(ex)   per (node, ch)
__device__ float g_hidden[NNODES * HID];  // GEMM1 output (pre-BN)
__device__ float g_bnsum[HID];
__device__ float g_bnsq[HID];
__device__ float g_ab[2 * HID];           // per-channel BN affine: a, b

// -------- kernel 0: zero accumulators --------
__global__ void zero_kernel() {
    int i = blockIdx.x * blockDim.x + threadIdx.x;  // 1.6M threads (float4 slots)
    float4 z = make_float4(0.f, 0.f, 0.f, 0.f);
    ((float4*)g_num)[i] = z;
    ((float4*)g_den)[i] = z;
    if (i < HID) { g_bnsum[i] = 0.f; g_bnsq[i] = 0.f; }
}

// -------- kernel 1: single pass over edges --------
// m = relu(feats[src]+e)+eps ; ex = exp(m) (softmax shift dropped: m in (0,~9])
// den[dst] += ex ; num[dst] += ex*m   via float4 vector reductions
__global__ void edge_kernel(const float* __restrict__ feats,
                            const float* __restrict__ eh,
                            const int* __restrict__ src,
                            const int* __restrict__ dst) {
    int t = blockIdx.x * blockDim.x + threadIdx.x;  // E*16 = 25.6M exactly
    int e = t >> 4;
    int c = (t & 15) << 2;
    int s = __ldg(src + e);
    int d = __ldg(dst + e);
    float4 f  = *(const float4*)(feats + (size_t)s * DIM + c);
    float4 ev = *(const float4*)(eh + (size_t)e * DIM + c);
    float m0 = fmaxf(f.x + ev.x, 0.f) + GEPS;
    float m1 = fmaxf(f.y + ev.y, 0.f) + GEPS;
    float m2 = fmaxf(f.z + ev.z, 0.f) + GEPS;
    float m3 = fmaxf(f.w + ev.w, 0.f) + GEPS;
    float e0 = __expf(m0), e1 = __expf(m1), e2 = __expf(m2), e3 = __expf(m3);
    size_t o = (size_t)d * DIM + c;
    atomicAdd((float4*)(g_den + o), make_float4(e0, e1, e2, e3));
    atomicAdd((float4*)(g_num + o), make_float4(e0 * m0, e1 * m1, e2 * m2, e3 * m3));
}

// -------- kernel 2: fused msgnorm + GEMM1 + BN-stats --------
// Tile: 128 nodes x 128 hid, 256 threads, 8x8 per thread, K=64.
// Staging computes x = feats + normalize(num/den)*||feats||*scale on the fly
// and stores it TRANSPOSED in smem so the inner loop is all LDS.128.
__global__ void __launch_bounds__(256, 2) gemm1_kernel(const float* __restrict__ feats,
                                                       const float* __restrict__ scale,
                                                       const float* __restrict__ W1,
                                                       const float* __restrict__ b1) {
    __shared__ float sxT[DIM][132];    // [k][node], pad 132 (multiple of 4 -> 16B aligned rows)
    __shared__ float sw[16][HID];      // W1 k-chunk
    __shared__ float red_s[HID];
    __shared__ float red_q[HID];

    int tid = threadIdx.x;
    int m0 = blockIdx.x * 128;

    // ---- staging: fused MessageNorm, transposed store ----
    {
        int hw = tid >> 4;          // half-warp id 0..15
        int l = tid & 15;           // lane in half-warp
        int c = l * 4;
        float scl = __ldg(scale);
        #pragma unroll
        for (int p = 0; p < 8; p++) {
            int r = p * 16 + hw;    // node row within tile 0..127
            int n = m0 + r;
            float4 f = make_float4(0.f, 0.f, 0.f, 0.f);
            float4 nu = f, de = f;
            if (n < NNODES) {
                size_t o = (size_t)n * DIM + c;
                f = *(const float4*)(feats + o);
                nu = *(const float4*)(g_num + o);
                de = *(const float4*)(g_den + o);
            }
            float4 h;
            h.x = de.x > 0.f ? nu.x / de.x : 0.f;
            h.y = de.y > 0.f ? nu.y / de.y : 0.f;
            h.z = de.z > 0.f ? nu.z / de.z : 0.f;
            h.w = de.w > 0.f ? nu.w / de.w : 0.f;
            float hs = h.x * h.x + h.y * h.y + h.z * h.z + h.w * h.w;
            float fs = f.x * f.x + f.y * f.y + f.z * f.z + f.w * f.w;
            #pragma unroll
            for (int off = 8; off; off >>= 1) {
                hs += __shfl_xor_sync(0xffffffffu, hs, off);
                fs += __shfl_xor_sync(0xffffffffu, fs, off);
            }
            float kk = sqrtf(fs) * scl / fmaxf(sqrtf(hs), NORM_EPSC);
            sxT[c + 0][r] = f.x + h.x * kk;
            sxT[c + 1][r] = f.y + h.y * kk;
            sxT[c + 2][r] = f.z + h.z * kk;
            sxT[c + 3][r] = f.w + h.w * kk;
        }
    }

    int ty = tid >> 4;   // node group: nodes m0 + ty*8 .. +7
    int tx = tid & 15;   // hid group:  hid  tx*8 .. +7

    float acc[8][8];
    #pragma unroll
    for (int i = 0; i < 8; i++)
        #pragma unroll
        for (int j = 0; j < 8; j++) acc[i][j] = 0.f;

    #pragma unroll
    for (int kc = 0; kc < 4; kc++) {
        __syncthreads();
        // load W1 rows kc*16 .. +15 : 2048 floats = 512 float4
        const float4* wsrc = (const float4*)(W1 + (size_t)kc * 16 * HID);
        ((float4*)sw)[tid] = wsrc[tid];
        ((float4*)sw)[tid + 256] = wsrc[tid + 256];
        __syncthreads();
        #pragma unroll
        for (int kk = 0; kk < 16; kk++) {
            float4 a0 = *(float4*)&sxT[kc * 16 + kk][ty * 8];
            float4 a1 = *(float4*)&sxT[kc * 16 + kk][ty * 8 + 4];
            float4 b0 = *(float4*)&sw[kk][tx * 8];
            float4 b1v = *(float4*)&sw[kk][tx * 8 + 4];
            float a[8] = {a0.x, a0.y, a0.z, a0.w, a1.x, a1.y, a1.z, a1.w};
            float b[8] = {b0.x, b0.y, b0.z, b0.w, b1v.x, b1v.y, b1v.z, b1v.w};
            #pragma unroll
            for (int i = 0; i < 8; i++)
                #pragma unroll
                for (int j = 0; j < 8; j++)
                    acc[i][j] += a[i] * b[j];
        }
    }

    // ---- epilogue: +b1, write hidden, BN partial stats ----
    __syncthreads();
    if (tid < HID) { red_s[tid] = 0.f; red_q[tid] = 0.f; }
    __syncthreads();

    float bb[8];
    #pragma unroll
    for (int j = 0; j < 8; j++) bb[j] = __ldg(b1 + tx * 8 + j);
    float ps[8], pq[8];
    #pragma unroll
    for (int j = 0; j < 8; j++) { ps[j] = 0.f; pq[j] = 0.f; }

    #pragma unroll
    for (int i = 0; i < 8; i++) {
        int n = m0 + ty * 8 + i;
        if (n < NNODES) {
            float h[8];
            #pragma unroll
            for (int j = 0; j < 8; j++) {
                h[j] = acc[i][j] + bb[j];
                ps[j] += h[j];
                pq[j] += h[j] * h[j];
            }
            float* dstp = g_hidden + (size_t)n * HID + tx * 8;
            *(float4*)(dstp)     = make_float4(h[0], h[1], h[2], h[3]);
            *(float4*)(dstp + 4) = make_float4(h[4], h[5], h[6], h[7]);
        }
    }
    #pragma unroll
    for (int j = 0; j < 8; j++) {
        atomicAdd(&red_s[tx * 8 + j], ps[j]);
        atomicAdd(&red_q[tx * 8 + j], pq[j]);
    }
    __syncthreads();
    if (tid < HID) {
        atomicAdd(&g_bnsum[tid], red_s[tid]);
        atomicAdd(&g_bnsq[tid], red_q[tid]);
    }
}

// -------- kernel 3: finalize BN affine --------
__global__ void bnfin_kernel(const float* __restrict__ gamma,
                             const float* __restrict__ beta) {
    int c = threadIdx.x;
    float mean = g_bnsum[c] * (1.0f / NNODES);
    float var = g_bnsq[c] * (1.0f / NNODES) - mean * mean;
    float inv = rsqrtf(var + BN_EPSC);
    float a = __ldg(gamma + c) * inv;
    g_ab[c] = a;
    g_ab[HID + c] = __ldg(beta + c) - mean * a;
}

// -------- kernel 4: out = relu(bn(hidden)) @ W2 + b2 --------
// Tile: 128 nodes x 64 out, 256 threads, 8x4 per thread, K=128 in 4 chunks.
// BN+ReLU applied during transposed staging.
__global__ void __launch_bounds__(256) gemm2_kernel(const float* __restrict__ W2,
                                                    const float* __restrict__ b2,
                                                    float* __restrict__ out) {
    __shared__ float shT[32][132];   // [k - k0][node], pad 132 for 16B-aligned rows
    __shared__ float sw2[32][ODIM];
    __shared__ float sab[2 * HID];

    int tid = threadIdx.x;
    int m0 = blockIdx.x * 128;
    sab[tid] = g_ab[tid];            // 256 == 2*HID

    int ty = tid >> 4;   // node group (8 nodes)
    int tx = tid & 15;   // out group (4 outs)

    float acc[8][4];
    #pragma unroll
    for (int i = 0; i < 8; i++)
        #pragma unroll
        for (int j = 0; j < 4; j++) acc[i][j] = 0.f;

    #pragma unroll
    for (int kc = 0; kc < 4; kc++) {
        int k0 = kc * 32;
        __syncthreads();
        // W2 chunk: 32x64 = 2048 floats = 512 float4
        const float4* wsrc = (const float4*)(W2 + (size_t)k0 * ODIM);
        ((float4*)sw2)[tid] = wsrc[tid];
        ((float4*)sw2)[tid + 256] = wsrc[tid + 256];
        // hidden chunk, BN+ReLU, transposed: 128 nodes x 32 ch = 1024 float4
        #pragma unroll
        for (int p = 0; p < 4; p++) {
            int flat = p * 256 + tid;
            int r = flat >> 3;       // node row 0..127
            int q = flat & 7;        // float4 index within 32 ch
            int n = m0 + r;
            int ch = k0 + q * 4;
            float4 v = make_float4(0.f, 0.f, 0.f, 0.f);
            if (n < NNODES) {
                v = *(const float4*)(g_hidden + (size_t)n * HID + ch);
                v.x = fmaxf(v.x * sab[ch + 0] + sab[HID + ch + 0], 0.f);
                v.y = fmaxf(v.y * sab[ch + 1] + sab[HID + ch + 1], 0.f);
                v.z = fmaxf(v.z * sab[ch + 2] + sab[HID + ch + 2], 0.f);
                v.w = fmaxf(v.w * sab[ch + 3] + sab[HID + ch + 3], 0.f);
            }
            shT[q * 4 + 0][r] = v.x;
            shT[q * 4 + 1][r] = v.y;
            shT[q * 4 + 2][r] = v.z;
            shT[q * 4 + 3][r] = v.w;
        }
        __syncthreads();
        #pragma unroll
        for (int kk = 0; kk < 32; kk++) {
            float4 a0 = *(float4*)&shT[kk][ty * 8];
            float4 a1 = *(float4*)&shT[kk][ty * 8 + 4];
            float4 b = *(float4*)&sw2[kk][tx * 4];
            float a[8] = {a0.x, a0.y, a0.z, a0.w, a1.x, a1.y, a1.z, a1.w};
            #pragma unroll
            for (int i = 0; i < 8; i++) {
                acc[i][0] += a[i] * b.x;
                acc[i][1] += a[i] * b.y;
                acc[i][2] += a[i] * b.z;
                acc[i][3] += a[i] * b.w;
            }
        }
    }

    float4 bv = *(const float4*)(b2 + tx * 4);
    #pragma unroll
    for (int i = 0; i < 8; i++) {
        int n = m0 + ty * 8 + i;
        if (n < NNODES) {
            float4 o = make_float4(acc[i][0] + bv.x, acc[i][1] + bv.y,
                                   acc[i][2] + bv.z, acc[i][3] + bv.w);
            *(float4*)(out + (size_t)n * ODIM + tx * 4) = o;
        }
    }
}

// -------- host launcher --------
extern "C" void kernel_launch(void* const* d_in, const int* in_sizes, int n_in,
                              void* d_out, int out_size) {
    const float *feats = nullptr, *edge_h = nullptr, *W1 = nullptr, *b1 = nullptr;
    const float *gamma = nullptr, *bnb = nullptr, *W2 = nullptr, *b2 = nullptr, *scale = nullptr;
    const int *src = nullptr, *dst = nullptr;
    int nE = 0, nW = 0, nH = 0;
    for (int i = 0; i < n_in; i++) {
        int s = in_sizes[i];
        const void* p = d_in[i];
        if (s == NNODES * DIM) feats = (const float*)p;
        else if (s == NEDGES * DIM) edge_h = (const float*)p;
        else if (s == NEDGES) { if (nE++ == 0) src = (const int*)p; else dst = (const int*)p; }
        else if (s == DIM * HID) { if (nW++ == 0) W1 = (const float*)p; else W2 = (const float*)p; }
        else if (s == HID) {
            if (nH == 0) b1 = (const float*)p;
            else if (nH == 1) gamma = (const float*)p;
            else bnb = (const float*)p;
            nH++;
        }
        else if (s == ODIM) b2 = (const float*)p;
        else if (s == 1) scale = (const float*)p;
    }

    zero_kernel<<<(NNODES * DIM / 4 + 255) / 256, 256>>>();
    edge_kernel<<<(NEDGES * 16) / 256, 256>>>(feats, edge_h, src, dst);
    gemm1_kernel<<<(NNODES + 127) / 128, 256>>>(feats, scale, W1, b1);
    bnfin_kernel<<<1, HID>>>(gamma, bnb);
    gemm2_kernel<<<(NNODES + 127) / 128, 256>>>(W2, b2, (float*)d_out);
}

// round 5
// speedup vs baseline: 1.2070x; 1.1263x over previous
#include <cuda_runtime.h>
#include <cuda_bf16.h>

#define NNODES 100000
#define NEDGES 1600000
#define DIM 64
#define HID 128
#define ODIM 64
#define GEPS 1e-7f
#define BN_EPSC 1e-5f
#define NORM_EPSC 1e-12f

#define SCAN_CHUNK 512
#define NB1 ((NNODES + SCAN_CHUNK - 1) / SCAN_CHUNK)   // 196

// -------- scratch (device globals; no allocation allowed) --------
__device__ int   g_cnt[NNODES];          // in-degree histogram
__device__ int   g_off[NNODES + 1];      // CSR offsets
__device__ int   g_fill[NNODES];         // running fill pointers (scatter)
__device__ int   g_bsum[256];            // scan block sums
__device__ int   g_boff[256];            // scanned block offsets
__device__ int   g_eid[NEDGES];          // edge ids sorted by dst
__device__ float g_x[NNODES * DIM];      // post-MessageNorm features
__device__ float g_hidden[NNODES * HID]; // GEMM1 output (pre-BN)
__device__ float g_bnsum[HID];
__device__ float g_bnsq[HID];

// -------- kernel 0: zero histogram + BN stats --------
__global__ void zero_kernel() {
    int i = blockIdx.x * blockDim.x + threadIdx.x;
    if (i < NNODES) g_cnt[i] = 0;
    if (i < HID) { g_bnsum[i] = 0.f; g_bnsq[i] = 0.f; }
}

// -------- kernel 1: in-degree histogram --------
__global__ void hist_kernel(const int* __restrict__ dst) {
    int e = blockIdx.x * blockDim.x + threadIdx.x;
    if (e < NEDGES) atomicAdd(&g_cnt[__ldg(dst + e)], 1);
}

// -------- kernel 2a: per-chunk sums --------
__global__ void __launch_bounds__(256) scan1_kernel() {
    __shared__ int s[256];
    int b = blockIdx.x, tid = threadIdx.x;
    int base = b * SCAN_CHUNK;
    int i0 = base + 2 * tid, i1 = i0 + 1;
    int c0 = (i0 < NNODES) ? g_cnt[i0] : 0;
    int c1 = (i1 < NNODES) ? g_cnt[i1] : 0;
    s[tid] = c0 + c1;
    __syncthreads();
    #pragma unroll
    for (int st = 128; st; st >>= 1) {
        if (tid < st) s[tid] += s[tid + st];
        __syncthreads();
    }
    if (tid == 0) g_bsum[b] = s[0];
}

// -------- kernel 2b: scan the chunk sums (single block) --------
__global__ void __launch_bounds__(256) scan2_kernel() {
    __shared__ int s[256];
    int tid = threadIdx.x;
    int v = (tid < NB1) ? g_bsum[tid] : 0;
    s[tid] = v;
    __syncthreads();
    #pragma unroll
    for (int st = 1; st < 256; st <<= 1) {
        int t = (tid >= st) ? s[tid - st] : 0;
        __syncthreads();
        s[tid] += t;
        __syncthreads();
    }
    g_boff[tid] = s[tid] - v;   // exclusive
}

// -------- kernel 2c: final offsets (and fill pointers) --------
__global__ void __launch_bounds__(256) scan3_kernel() {
    __shared__ int s[256];
    int b = blockIdx.x, tid = threadIdx.x;
    int base = b * SCAN_CHUNK;
    int i0 = base + 2 * tid, i1 = i0 + 1;
    int c0 = (i0 < NNODES) ? g_cnt[i0] : 0;
    int c1 = (i1 < NNODES) ? g_cnt[i1] : 0;
    int p = c0 + c1;
    s[tid] = p;
    __syncthreads();
    #pragma unroll
    for (int st = 1; st < 256; st <<= 1) {
        int t = (tid >= st) ? s[tid - st] : 0;
        __syncthreads();
        s[tid] += t;
        __syncthreads();
    }
    int excl = g_boff[b] + s[tid] - p;
    if (i0 < NNODES) { g_off[i0] = excl; g_fill[i0] = excl; }
    if (i1 < NNODES) { g_off[i1] = excl + c0; g_fill[i1] = excl + c0; }
    if (b == 0 && tid == 0) g_off[NNODES] = NEDGES;
}

// -------- kernel 3: scatter edge ids into CSR order --------
__global__ void scatter_kernel(const int* __restrict__ dst) {
    int e = blockIdx.x * blockDim.x + threadIdx.x;
    if (e < NEDGES) {
        int d = __ldg(dst + e);
        int pos = atomicAdd(&g_fill[d], 1);
        g_eid[pos] = e;
    }
}

// -------- kernel 4: gather-aggregate + fused MessageNorm --------
// 16 threads per node (4 channels each). num/den in registers; no float atomics.
// m = relu(feats[src]+e)+eps; ex = exp(m) (shift-free softmax: m in (0,~9]).
__global__ void __launch_bounds__(256) gather_kernel(const float* __restrict__ feats,
                                                     const float* __restrict__ eh,
                                                     const int* __restrict__ src,
                                                     const float* __restrict__ scale) {
    int t = blockIdx.x * blockDim.x + threadIdx.x;  // N*16 = 1.6M exactly
    int n = t >> 4;
    int c = (t & 15) << 2;
    int base = __ldg(g_off + n);
    int end  = __ldg(g_off + n + 1);

    float4 num = make_float4(0.f, 0.f, 0.f, 0.f);
    float4 den = make_float4(0.f, 0.f, 0.f, 0.f);
    for (int i = base; i < end; i++) {
        int e = __ldg(g_eid + i);
        int s = __ldg(src + e);
        float4 f  = *(const float4*)(feats + (size_t)s * DIM + c);
        float4 ev = __ldg((const float4*)(eh + (size_t)e * DIM + c));
        float m0 = fmaxf(f.x + ev.x, 0.f) + GEPS;
        float m1 = fmaxf(f.y + ev.y, 0.f) + GEPS;
        float m2 = fmaxf(f.z + ev.z, 0.f) + GEPS;
        float m3 = fmaxf(f.w + ev.w, 0.f) + GEPS;
        float e0 = __expf(m0), e1 = __expf(m1), e2 = __expf(m2), e3 = __expf(m3);
        den.x += e0; den.y += e1; den.z += e2; den.w += e3;
        num.x += e0 * m0; num.y += e1 * m1; num.z += e2 * m2; num.w += e3 * m3;
    }

    float4 h;
    h.x = den.x > 0.f ? num.x / den.x : 0.f;
    h.y = den.y > 0.f ? num.y / den.y : 0.f;
    h.z = den.z > 0.f ? num.z / den.z : 0.f;
    h.w = den.w > 0.f ? num.w / den.w : 0.f;

    size_t o = (size_t)n * DIM + c;
    float4 f = *(const float4*)(feats + o);
    float hs = h.x * h.x + h.y * h.y + h.z * h.z + h.w * h.w;
    float fs = f.x * f.x + f.y * f.y + f.z * f.z + f.w * f.w;
    #pragma unroll
    for (int off = 8; off; off >>= 1) {   // xor<16 stays within the 16-lane group
        hs += __shfl_xor_sync(0xffffffffu, hs, off);
        fs += __shfl_xor_sync(0xffffffffu, fs, off);
    }
    float kk = sqrtf(fs) * __ldg(scale) / fmaxf(sqrtf(hs), NORM_EPSC);
    float4 x = make_float4(f.x + h.x * kk, f.y + h.y * kk,
                           f.z + h.z * kk, f.w + h.w * kk);
    *(float4*)(g_x + o) = x;
}

// -------- kernel 5: GEMM1 (x@W1+b1) + BN stats --------
// 128 nodes x 128 hid tile, 256 threads, 8x8 per thread, x transposed in smem.
__global__ void __launch_bounds__(256, 2) gemm1_kernel(const float* __restrict__ W1,
                                                       const float* __restrict__ b1) {
    __shared__ float sxT[DIM][132];    // [k][node], rows 16B-aligned
    __shared__ float sw[16][HID];
    __shared__ float red_s[HID];
    __shared__ float red_q[HID];

    int tid = threadIdx.x;
    int m0 = blockIdx.x * 128;

    // staging: transposed load of g_x
    {
        int hw = tid >> 4;
        int c = (tid & 15) * 4;
        #pragma unroll
        for (int p = 0; p < 8; p++) {
            int r = p * 16 + hw;
            int n = m0 + r;
            float4 v = make_float4(0.f, 0.f, 0.f, 0.f);
            if (n < NNODES) v = *(const float4*)(g_x + (size_t)n * DIM + c);
            sxT[c + 0][r] = v.x;
            sxT[c + 1][r] = v.y;
            sxT[c + 2][r] = v.z;
            sxT[c + 3][r] = v.w;
        }
    }

    int ty = tid >> 4;
    int tx = tid & 15;

    float acc[8][8];
    #pragma unroll
    for (int i = 0; i < 8; i++)
        #pragma unroll
        for (int j = 0; j < 8; j++) acc[i][j] = 0.f;

    #pragma unroll
    for (int kc = 0; kc < 4; kc++) {
        __syncthreads();
        const float4* wsrc = (const float4*)(W1 + (size_t)kc * 16 * HID);
        ((float4*)sw)[tid] = wsrc[tid];
        ((float4*)sw)[tid + 256] = wsrc[tid + 256];
        __syncthreads();
        #pragma unroll
        for (int kk = 0; kk < 16; kk++) {
            float4 a0 = *(float4*)&sxT[kc * 16 + kk][ty * 8];
            float4 a1 = *(float4*)&sxT[kc * 16 + kk][ty * 8 + 4];
            float4 b0 = *(float4*)&sw[kk][tx * 8];
            float4 b1v = *(float4*)&sw[kk][tx * 8 + 4];
            float a[8] = {a0.x, a0.y, a0.z, a0.w, a1.x, a1.y, a1.z, a1.w};
            float b[8] = {b0.x, b0.y, b0.z, b0.w, b1v.x, b1v.y, b1v.z, b1v.w};
            #pragma unroll
            for (int i = 0; i < 8; i++)
                #pragma unroll
                for (int j = 0; j < 8; j++)
                    acc[i][j] += a[i] * b[j];
        }
    }

    __syncthreads();
    if (tid < HID) { red_s[tid] = 0.f; red_q[tid] = 0.f; }
    __syncthreads();

    float bb[8];
    #pragma unroll
    for (int j = 0; j < 8; j++) bb[j] = __ldg(b1 + tx * 8 + j);
    float ps[8], pq[8];
    #pragma unroll
    for (int j = 0; j < 8; j++) { ps[j] = 0.f; pq[j] = 0.f; }

    #pragma unroll
    for (int i = 0; i < 8; i++) {
        int n = m0 + ty * 8 + i;
        if (n < NNODES) {
            float h[8];
            #pragma unroll
            for (int j = 0; j < 8; j++) {
                h[j] = acc[i][j] + bb[j];
                ps[j] += h[j];
                pq[j] += h[j] * h[j];
            }
            float* dstp = g_hidden + (size_t)n * HID + tx * 8;
            *(float4*)(dstp)     = make_float4(h[0], h[1], h[2], h[3]);
            *(float4*)(dstp + 4) = make_float4(h[4], h[5], h[6], h[7]);
        }
    }
    #pragma unroll
    for (int j = 0; j < 8; j++) {
        atomicAdd(&red_s[tx * 8 + j], ps[j]);
        atomicAdd(&red_q[tx * 8 + j], pq[j]);
    }
    __syncthreads();
    if (tid < HID) {
        atomicAdd(&g_bnsum[tid], red_s[tid]);
        atomicAdd(&g_bnsq[tid], red_q[tid]);
    }
}

// -------- kernel 6: out = relu(bn(hidden)) @ W2 + b2 (BN affine computed in-block)
__global__ void __launch_bounds__(256) gemm2_kernel(const float* __restrict__ gamma,
                                                    const float* __restrict__ beta,
                                                    const float* __restrict__ W2,
                                                    const float* __restrict__ b2,
                                                    float* __restrict__ out) {
    __shared__ float shT[32][132];
    __shared__ float sw2[32][ODIM];
    __shared__ float sab[2 * HID];

    int tid = threadIdx.x;
    int m0 = blockIdx.x * 128;

    if (tid < HID) {   // fold BN finalize into every block (cheap, removes a kernel)
        float mean = g_bnsum[tid] * (1.0f / NNODES);
        float var = g_bnsq[tid] * (1.0f / NNODES) - mean * mean;
        float inv = rsqrtf(var + BN_EPSC);
        float a = __ldg(gamma + tid) * inv;
        sab[tid] = a;
        sab[HID + tid] = __ldg(beta + tid) - mean * a;
    }

    int ty = tid >> 4;
    int tx = tid & 15;

    float acc[8][4];
    #pragma unroll
    for (int i = 0; i < 8; i++)
        #pragma unroll
        for (int j = 0; j < 4; j++) acc[i][j] = 0.f;

    #pragma unroll
    for (int kc = 0; kc < 4; kc++) {
        int k0 = kc * 32;
        __syncthreads();
        const float4* wsrc = (const float4*)(W2 + (size_t)k0 * ODIM);
        ((float4*)sw2)[tid] = wsrc[tid];
        ((float4*)sw2)[tid + 256] = wsrc[tid + 256];
        #pragma unroll
        for (int p = 0; p < 4; p++) {
            int flat = p * 256 + tid;
            int r = flat >> 3;
            int q = flat & 7;
            int n = m0 + r;
            int ch = k0 + q * 4;
            float4 v = make_float4(0.f, 0.f, 0.f, 0.f);
            if (n < NNODES) {
                v = *(const float4*)(g_hidden + (size_t)n * HID + ch);
                v.x = fmaxf(v.x * sab[ch + 0] + sab[HID + ch + 0], 0.f);
                v.y = fmaxf(v.y * sab[ch + 1] + sab[HID + ch + 1], 0.f);
                v.z = fmaxf(v.z * sab[ch + 2] + sab[HID + ch + 2], 0.f);
                v.w = fmaxf(v.w * sab[ch + 3] + sab[HID + ch + 3], 0.f);
            }
            shT[q * 4 + 0][r] = v.x;
            shT[q * 4 + 1][r] = v.y;
            shT[q * 4 + 2][r] = v.z;
            shT[q * 4 + 3][r] = v.w;
        }
        __syncthreads();
        #pragma unroll
        for (int kk = 0; kk < 32; kk++) {
            float4 a0 = *(float4*)&shT[kk][ty * 8];
            float4 a1 = *(float4*)&shT[kk][ty * 8 + 4];
            float4 b = *(float4*)&sw2[kk][tx * 4];
            float a[8] = {a0.x, a0.y, a0.z, a0.w, a1.x, a1.y, a1.z, a1.w};
            #pragma unroll
            for (int i = 0; i < 8; i++) {
                acc[i][0] += a[i] * b.x;
                acc[i][1] += a[i] * b.y;
                acc[i][2] += a[i] * b.z;
                acc[i][3] += a[i] * b.w;
            }
        }
    }

    float4 bv = *(const float4*)(b2 + tx * 4);
    #pragma unroll
    for (int i = 0; i < 8; i++) {
        int n = m0 + ty * 8 + i;
        if (n < NNODES) {
            float4 o = make_float4(acc[i][0] + bv.x, acc[i][1] + bv.y,
                                   acc[i][2] + bv.z, acc[i][3] + bv.w);
            *(float4*)(out + (size_t)n * ODIM + tx * 4) = o;
        }
    }
}

// -------- host launcher --------
extern "C" void kernel_launch(void* const* d_in, const int* in_sizes, int n_in,
                              void* d_out, int out_size) {
    const float *feats = nullptr, *edge_h = nullptr, *W1 = nullptr, *b1 = nullptr;
    const float *gamma = nullptr, *bnb = nullptr, *W2 = nullptr, *b2 = nullptr, *scale = nullptr;
    const int *src = nullptr, *dst = nullptr;
    int nE = 0, nW = 0, nH = 0;
    for (int i = 0; i < n_in; i++) {
        int s = in_sizes[i];
        const void* p = d_in[i];
        if (s == NNODES * DIM) feats = (const float*)p;
        else if (s == NEDGES * DIM) edge_h = (const float*)p;
        else if (s == NEDGES) { if (nE++ == 0) src = (const int*)p; else dst = (const int*)p; }
        else if (s == DIM * HID) { if (nW++ == 0) W1 = (const float*)p; else W2 = (const float*)p; }
        else if (s == HID) {
            if (nH == 0) b1 = (const float*)p;
            else if (nH == 1) gamma = (const float*)p;
            else bnb = (const float*)p;
            nH++;
        }
        else if (s == ODIM) b2 = (const float*)p;
        else if (s == 1) scale = (const float*)p;
    }

    zero_kernel<<<(NNODES + 255) / 256, 256>>>();
    hist_kernel<<<(NEDGES + 255) / 256, 256>>>(dst);
    scan1_kernel<<<NB1, 256>>>();
    scan2_kernel<<<1, 256>>>();
    scan3_kernel<<<NB1, 256>>>();
    scatter_kernel<<<(NEDGES + 255) / 256, 256>>>(dst);
    gather_kernel<<<(NNODES * 16) / 256, 256>>>(feats, edge_h, src, scale);
    gemm1_kernel<<<(NNODES + 127) / 128, 256>>>(W1, b1);
    gemm2_kernel<<<(NNODES + 127) / 128, 256>>>(gamma, bnb, W2, b2, (float*)d_out);
}